// round 8
// baseline (speedup 1.0000x reference)
#include <cuda_runtime.h>

// Shapes (fixed by reference setup_inputs):
//   e_src: (B=16, T=1024, F=8, C=256) float32
//   d_src: (16, 128) — declared int64 but JAX x64-disabled downcasts randint
//          to int32; probe the on-disk dtype deterministically.
//   output: (Bh=8, S=128, C=256) float32
static constexpr int T  = 1024;
static constexpr int F  = 8;
static constexpr int S  = 128;
static constexpr int C  = 256;
static constexpr int CSPLIT = 4;            // channel chunks per (b,s)
static constexpr int CCH = C / CSPLIT;      // 64 channels per block

// Grid (S, Bh, CSPLIT), 64 threads: thread = one channel of a 64-ch chunk.
// Small blocks (quantum = cnt rows x 256B) let the CTA scheduler balance the
// per-segment work variance (cnt in [0,15]) across SMs.
__global__ __launch_bounds__(64) void fs2_segment_mean_kernel(
    const float* __restrict__ e,      // (16,1024,8,256)
    const int*   __restrict__ dw,     // duration words (int32 view)
    float* __restrict__ out)          // (8,128,256)
{
    const int s   = blockIdx.x;   // 0..127
    const int b   = blockIdx.y;   // 0..7
    const int cz  = blockIdx.z;   // 0..3
    const int tid = threadIdx.x;  // 0..63

    // ---- dtype probe (first 256 words; durations are in [0,16)) ----------
    // int64 data: odd words == 0, even words < 16. int32 fails w.p. ~1.
    bool ok = true;
    #pragma unroll
    for (int k = 0; k < 4; ++k) {
        const int i = tid * 4 + k;
        const int w = dw[i];
        ok &= (i & 1) ? (w == 0) : (w >= 0 && w < 16);
    }
    const int is_i64 = __syncthreads_and(ok ? 1 : 0);

    // ---- segment start: sum of d[b, 0..s-1]; two warps, smem combine -----
    __shared__ int wsum[2];
    const int base_d = b * S;
    auto loadd = [&](int j) -> int {
        return is_i64 ? dw[(base_d + j) * 2] : dw[base_d + j];
    };
    int v = 0;
    if (tid < s)          v += loadd(tid);
    if (tid + 64 < s)     v += loadd(tid + 64);
    #pragma unroll
    for (int o = 16; o > 0; o >>= 1) v += __shfl_down_sync(0xffffffffu, v, o);
    if ((tid & 31) == 0) wsum[tid >> 5] = v;
    const int cnt = loadd(s);
    __syncthreads();

    int start = wsum[0] + wsum[1];
    int end = start + cnt;
    if (start > T) start = T;
    if (end   > T) end   = T;

    // ---- stream cnt frames x 8 features of this 64-channel chunk ---------
    float a0 = 0.f, a1 = 0.f, a2 = 0.f, a3 = 0.f;
    const float* base = e + (size_t)b * T * F * C + cz * CCH + tid;
    for (int t = start; t < end; ++t) {
        const float* p = base + (size_t)t * (F * C);
        a0 += __ldg(p + 0 * C);
        a1 += __ldg(p + 1 * C);
        a2 += __ldg(p + 2 * C);
        a3 += __ldg(p + 3 * C);
        a0 += __ldg(p + 4 * C);
        a1 += __ldg(p + 5 * C);
        a2 += __ldg(p + 6 * C);
        a3 += __ldg(p + 7 * C);
    }
    const float sum = (a0 + a1) + (a2 + a3);
    const float o = (cnt > 0) ? sum * (1.0f / (float)(cnt * F)) : 0.0f;
    out[((size_t)b * S + s) * C + cz * CCH + tid] = o;
}

extern "C" void kernel_launch(void* const* d_in, const int* in_sizes, int n_in,
                              void* d_out, int out_size)
{
    const float* e = (const float*)d_in[0];  // (16,1024,8,256) fp32
    const int*   d = (const int*)d_in[1];    // durations (int32 or int64 words)
    float*       o = (float*)d_out;          // (8,128,256) fp32

    dim3 grid(S, /*Bh=*/8, CSPLIT);
    fs2_segment_mean_kernel<<<grid, 64>>>(e, d, o);
}